// round 8
// baseline (speedup 1.0000x reference)
#include <cuda_runtime.h>
#include <cuda_bf16.h>

// Problem shape (fixed by reference setup_inputs)
#define B 64
#define T 4096
#define H 512

#define OCHUNKS 8            // o-split across blocks in proj
#define NTILE   64           // t-values per scores block
#define NTILES  (T / NTILE)  // 64 tiles per b

// Scratch (no allocation allowed in kernel_launch)
__device__ float  g_vpart[OCHUNKS][B][H];   // partial v per o-chunk
__device__ float  g_scores[B * T];          // raw scores [B, T]
__device__ float2 g_bpart[B][NTILES];       // per-(b,tile) online (max, sumexp)

// online-softmax combine
__device__ __forceinline__ float2 sm_combine(float2 a, float2 c) {
    const float m = fmaxf(a.x, c.x);
    float2 r;
    r.x = m;
    r.y = a.y * __expf(a.x - m) + c.y * __expf(c.x - m);
    return r;
}

// ---------------------------------------------------------------------------
// Kernel 1: partial v: g_vpart[z][b,h] = sum_{o in chunk z} hidden[b,o]*W[o,h]
// Grid: (H/32, B/4, 8) = 2048 blocks x 256 threads (8 warps = 8 o-groups of
// 8 o-steps within the 64-o chunk). BTILE=4. Full 64-warp occupancy; W L2
// traffic = 16MB. Deterministic partials, summed by scores during sv staging.
// ---------------------------------------------------------------------------
__global__ void __launch_bounds__(256, 8)
proj_hidden_kernel(const float* __restrict__ hidden,
                   const float* __restrict__ W) {
    const int b0 = blockIdx.y * 4;
    const int h0 = blockIdx.x * 32;
    const int oc = blockIdx.z;            // o-chunk, 64 o's
    const int hl = threadIdx.x & 31;      // h lane
    const int og = threadIdx.x >> 5;      // o-group 0..7 (warp-uniform)

    __shared__ float sh[4][64];
    // stage 4 hidden rows x 64 o's: 256 floats / 256 threads -> 1 float each
    {
        const int r = threadIdx.x >> 6;           // 0..3
        const int c = threadIdx.x & 63;           // 0..63
        sh[r][c] = hidden[(size_t)(b0 + r) * H + oc * 64 + c];
    }
    __syncthreads();

    const int obase = oc * 64 + og * 8;
    const float* __restrict__ wp = W + (size_t)obase * H + h0 + hl;
    const int ol = og * 8;
    float acc0 = 0.0f, acc1 = 0.0f, acc2 = 0.0f, acc3 = 0.0f;
#pragma unroll
    for (int o = 0; o < 8; ++o) {
        const float w = wp[(size_t)o * H];
        acc0 += sh[0][ol + o] * w;
        acc1 += sh[1][ol + o] * w;
        acc2 += sh[2][ol + o] * w;
        acc3 += sh[3][ol + o] * w;
    }

    __shared__ float part[8][4][32];
    part[og][0][hl] = acc0;
    part[og][1][hl] = acc1;
    part[og][2][hl] = acc2;
    part[og][3][hl] = acc3;
    __syncthreads();
    if (threadIdx.x < 128) {
        const int bb = threadIdx.x >> 5;   // 0..3
        const int hh = threadIdx.x & 31;
        float r = 0.0f;
#pragma unroll
        for (int g = 0; g < 8; ++g) r += part[g][bb][hh];
        g_vpart[oc][b0 + bb][h0 + hh] = r;
    }
}

// ---------------------------------------------------------------------------
// Kernel 2: scores[b,t] = enc[b,t,:] . v[b,:]  +  per-(b,tile) online (m,s).
// Grid: (T/64, B). 256 threads = 8 warps; each warp owns 8 consecutive t,
// ONE t at a time (MLP_p1=4 proven). After the butterfly reduce every lane
// holds acc, so online (m,s) tracking is redundant-per-lane and overlaps the
// next t's loads. Block combine 8 warps -> g_bpart[b][tile].
// __ldcs: enc is a single-use 512MB stream, evict-first.
// ---------------------------------------------------------------------------
__global__ void scores_kernel(const float* __restrict__ enc) {
    const int b    = blockIdx.y;
    const int tile = blockIdx.x;          // 64 t-values per block
    const int tid  = threadIdx.x;         // 256
    const int warp = tid >> 5;
    const int lane = tid & 31;

    __shared__ float sv[H];
    {
        float2 s;
        s.x = 0.0f; s.y = 0.0f;
#pragma unroll
        for (int z = 0; z < OCHUNKS; ++z) {
            const float2 p = reinterpret_cast<const float2*>(g_vpart[z][b])[tid];
            s.x += p.x; s.y += p.y;
        }
        reinterpret_cast<float2*>(sv)[tid] = s;
    }
    __syncthreads();

    const float4* __restrict__ vb = reinterpret_cast<const float4*>(sv);
    const float4* __restrict__ base =
        reinterpret_cast<const float4*>(enc + (size_t)b * T * H);

    float m_run = -1e30f, s_run = 0.0f;

#pragma unroll
    for (int i = 0; i < 8; ++i) {
        const int t = tile * 64 + warp * 8 + i;
        const float4* __restrict__ row = base + (size_t)t * (H / 4);

        float acc = 0.0f;
#pragma unroll
        for (int k = 0; k < 4; ++k) {
            const float4 x = __ldcs(row + lane + k * 32);
            const float4 w = vb[lane + k * 32];
            acc += x.x * w.x + x.y * w.y + x.z * w.z + x.w * w.w;
        }
#pragma unroll
        for (int off = 16; off; off >>= 1)
            acc += __shfl_xor_sync(0xffffffffu, acc, off);
        if (lane == 0) g_scores[b * T + t] = acc;

        // online (m, s) — identical on all lanes
        const float m_new = fmaxf(m_run, acc);
        s_run = s_run * __expf(m_run - m_new) + __expf(acc - m_new);
        m_run = m_new;
    }

    // combine 8 warps -> block (m, s)
    __shared__ float2 wred[8];
    if (lane == 0) { wred[warp].x = m_run; wred[warp].y = s_run; }
    __syncthreads();
    if (tid < 8) {
        float2 v = wred[tid];
#pragma unroll
        for (int off = 4; off; off >>= 1) {
            float2 o;
            o.x = __shfl_xor_sync(0x000000ffu, v.x, off);
            o.y = __shfl_xor_sync(0x000000ffu, v.y, off);
            v = sm_combine(v, o);
        }
        if (tid == 0) g_bpart[b][tile] = v;
    }
}

// ---------------------------------------------------------------------------
// Kernel 3: scale pass. Grid (T/1024, B) = 256 blocks x 256 threads.
// Each block tree-combines the 64 tile partials (L2 hits) then writes
// exp(x - m) / S for its 1024 t's (float4 per thread).
// ---------------------------------------------------------------------------
__global__ void scale_kernel(float* __restrict__ out) {
    const int b   = blockIdx.y;
    const int seg = blockIdx.x;           // 1024 t-values per block
    const int tid = threadIdx.x;          // 256

    __shared__ float2 ms;
    if (tid < 32) {
        // lanes 0..31 combine entries (lane, lane+32), then 5-step shfl tree
        float2 v = sm_combine(g_bpart[b][tid], g_bpart[b][tid + 32]);
#pragma unroll
        for (int off = 16; off; off >>= 1) {
            float2 o;
            o.x = __shfl_xor_sync(0xffffffffu, v.x, off);
            o.y = __shfl_xor_sync(0xffffffffu, v.y, off);
            v = sm_combine(v, o);
        }
        if (tid == 0) ms = v;
    }
    __syncthreads();

    const float m   = ms.x;
    const float inv = 1.0f / ms.y;

    const int idx = b * T + seg * 1024 + tid * 4;
    const float4 x = *reinterpret_cast<const float4*>(g_scores + idx);
    float4 y;
    y.x = __expf(x.x - m) * inv;
    y.y = __expf(x.y - m) * inv;
    y.z = __expf(x.z - m) * inv;
    y.w = __expf(x.w - m) * inv;
    *reinterpret_cast<float4*>(out + idx) = y;
}

// ---------------------------------------------------------------------------
extern "C" void kernel_launch(void* const* d_in, const int* in_sizes, int n_in,
                              void* d_out, int out_size) {
    const float* hidden = (const float*)d_in[0];   // [B, H]
    const float* enc    = (const float*)d_in[1];   // [B, T, H]
    const float* W      = (const float*)d_in[2];   // [H, H]
    // d_in[3] = bias: cancels under softmax, unused.
    float* out = (float*)d_out;                    // [B, 1, T]

    {
        dim3 grid(H / 32, B / 4, OCHUNKS);
        proj_hidden_kernel<<<grid, 256>>>(hidden, W);
    }
    {
        dim3 grid(T / NTILE, B);
        scores_kernel<<<grid, 256>>>(enc);
    }
    {
        dim3 grid(T / 1024, B);
        scale_kernel<<<grid, 256>>>(out);
    }
}

// round 9
// speedup vs baseline: 1.0234x; 1.0234x over previous
#include <cuda_runtime.h>
#include <cuda_bf16.h>

// Problem shape (fixed by reference setup_inputs)
#define B 64
#define T 4096
#define H 512

#define OCHUNKS 4            // o-split across blocks in proj
#define NTILE   64           // t-values per scores block
#define NTILES  (T / NTILE)  // 64 tiles per b

// Scratch (no allocation allowed in kernel_launch)
__device__ float  g_vpart[OCHUNKS][B][H];   // partial v per o-chunk
__device__ float  g_scores[B * T];          // raw scores [B, T]
__device__ float2 g_bpart[B][NTILES];       // per-(b,tile) (max, sumexp)

// online-softmax combine
__device__ __forceinline__ float2 sm_combine(float2 a, float2 c) {
    const float m = fmaxf(a.x, c.x);
    float2 r;
    r.x = m;
    r.y = a.y * __expf(a.x - m) + c.y * __expf(c.x - m);
    return r;
}

// ---------------------------------------------------------------------------
// Kernel 1: partial v: g_vpart[z][b,h] = sum_{o in chunk z} hidden[b,o]*W[o,h]
// Grid: (H/32, B/4, 4) = 1024 blocks x 256 threads (8 warps = 8 o-groups of
// 16 o-steps within the 128-o chunk). BTILE=4. ~83% occ; W L2 traffic = 16MB.
// (R7-proven config: OCHUNKS=8 regressed.)
// ---------------------------------------------------------------------------
__global__ void __launch_bounds__(256, 8)
proj_hidden_kernel(const float* __restrict__ hidden,
                   const float* __restrict__ W) {
    const int b0 = blockIdx.y * 4;
    const int h0 = blockIdx.x * 32;
    const int oc = blockIdx.z;            // o-chunk, 128 o's
    const int hl = threadIdx.x & 31;      // h lane
    const int og = threadIdx.x >> 5;      // o-group 0..7 (warp-uniform)

    __shared__ float sh[4][128];
    // stage 4 hidden rows x 128 o's: 512 floats / 256 threads -> float2 each
    {
        const int r = threadIdx.x >> 6;           // 0..3
        const int c = threadIdx.x & 63;           // float2 slot 0..63
        reinterpret_cast<float2*>(sh[r])[c] =
            reinterpret_cast<const float2*>(hidden + (size_t)(b0 + r) * H + oc * 128)[c];
    }
    __syncthreads();

    const int obase = oc * 128 + og * 16;
    const float* __restrict__ wp = W + (size_t)obase * H + h0 + hl;
    const int ol = og * 16;
    float acc0 = 0.0f, acc1 = 0.0f, acc2 = 0.0f, acc3 = 0.0f;
#pragma unroll
    for (int o = 0; o < 16; ++o) {
        const float w = wp[(size_t)o * H];
        acc0 += sh[0][ol + o] * w;
        acc1 += sh[1][ol + o] * w;
        acc2 += sh[2][ol + o] * w;
        acc3 += sh[3][ol + o] * w;
    }

    __shared__ float part[8][4][32];
    part[og][0][hl] = acc0;
    part[og][1][hl] = acc1;
    part[og][2][hl] = acc2;
    part[og][3][hl] = acc3;
    __syncthreads();
    if (threadIdx.x < 128) {
        const int bb = threadIdx.x >> 5;   // 0..3
        const int hh = threadIdx.x & 31;
        float r = 0.0f;
#pragma unroll
        for (int g = 0; g < 8; ++g) r += part[g][bb][hh];
        g_vpart[oc][b0 + bb][h0 + hh] = r;
    }
}

// ---------------------------------------------------------------------------
// Kernel 2: scores[b,t] = enc[b,t,:] . v[b,:], plus a BLOCK-TAIL (m, sumexp)
// reduce over the 64 t's -> g_bpart[b][tile]. Inner loop identical to R7
// (MLP_p1=4 proven; no exp on the load path). __ldcs: single-use 512MB stream.
// ---------------------------------------------------------------------------
__global__ void scores_kernel(const float* __restrict__ enc) {
    const int b    = blockIdx.y;
    const int tile = blockIdx.x;          // 64 t-values per block
    const int tid  = threadIdx.x;         // 256
    const int warp = tid >> 5;
    const int lane = tid & 31;

    __shared__ float sv[H];
    {
        const float2 p0 = reinterpret_cast<const float2*>(g_vpart[0][b])[tid];
        const float2 p1 = reinterpret_cast<const float2*>(g_vpart[1][b])[tid];
        const float2 p2 = reinterpret_cast<const float2*>(g_vpart[2][b])[tid];
        const float2 p3 = reinterpret_cast<const float2*>(g_vpart[3][b])[tid];
        float2 s;
        s.x = (p0.x + p1.x) + (p2.x + p3.x);
        s.y = (p0.y + p1.y) + (p2.y + p3.y);
        reinterpret_cast<float2*>(sv)[tid] = s;
    }
    __syncthreads();

    const float4* __restrict__ vb = reinterpret_cast<const float4*>(sv);
    const float4* __restrict__ base =
        reinterpret_cast<const float4*>(enc + (size_t)b * T * H);

    __shared__ float s_acc[64];           // this block's 64 raw scores

#pragma unroll
    for (int i = 0; i < 8; ++i) {
        const int t = tile * 64 + warp * 8 + i;
        const float4* __restrict__ row = base + (size_t)t * (H / 4);

        float acc = 0.0f;
#pragma unroll
        for (int k = 0; k < 4; ++k) {
            const float4 x = __ldcs(row + lane + k * 32);
            const float4 w = vb[lane + k * 32];
            acc += x.x * w.x + x.y * w.y + x.z * w.z + x.w * w.w;
        }
#pragma unroll
        for (int off = 16; off; off >>= 1)
            acc += __shfl_xor_sync(0xffffffffu, acc, off);
        if (lane == 0) {
            g_scores[b * T + t] = acc;
            s_acc[warp * 8 + i] = acc;
        }
    }

    // block tail: (m, sumexp) over the 64 scores (off the load path)
    __syncthreads();
    if (tid < 32) {
        const float v0 = s_acc[tid];
        const float v1 = s_acc[tid + 32];
        float m = fmaxf(v0, v1);
#pragma unroll
        for (int off = 16; off; off >>= 1)
            m = fmaxf(m, __shfl_xor_sync(0xffffffffu, m, off));
        float e = __expf(v0 - m) + __expf(v1 - m);
#pragma unroll
        for (int off = 16; off; off >>= 1)
            e += __shfl_xor_sync(0xffffffffu, e, off);
        if (tid == 0) {
            float2 r; r.x = m; r.y = e;
            g_bpart[b][tile] = r;
        }
    }
}

// ---------------------------------------------------------------------------
// Kernel 3: scale pass. Grid (T/1024, B) = 256 blocks x 256 threads.
// Each block tree-combines the 64 tile partials (L2 hits) then writes
// exp(x - m) / S for its 1024 t's (float4 per thread).
// ---------------------------------------------------------------------------
__global__ void scale_kernel(float* __restrict__ out) {
    const int b   = blockIdx.y;
    const int seg = blockIdx.x;           // 1024 t-values per block
    const int tid = threadIdx.x;          // 256

    __shared__ float2 ms;
    if (tid < 32) {
        float2 v = sm_combine(g_bpart[b][tid], g_bpart[b][tid + 32]);
#pragma unroll
        for (int off = 16; off; off >>= 1) {
            float2 o;
            o.x = __shfl_xor_sync(0xffffffffu, v.x, off);
            o.y = __shfl_xor_sync(0xffffffffu, v.y, off);
            v = sm_combine(v, o);
        }
        if (tid == 0) ms = v;
    }
    __syncthreads();

    const float m   = ms.x;
    const float inv = 1.0f / ms.y;

    const int idx = b * T + seg * 1024 + tid * 4;
    const float4 x = *reinterpret_cast<const float4*>(g_scores + idx);
    float4 y;
    y.x = __expf(x.x - m) * inv;
    y.y = __expf(x.y - m) * inv;
    y.z = __expf(x.z - m) * inv;
    y.w = __expf(x.w - m) * inv;
    *reinterpret_cast<float4*>(out + idx) = y;
}

// ---------------------------------------------------------------------------
extern "C" void kernel_launch(void* const* d_in, const int* in_sizes, int n_in,
                              void* d_out, int out_size) {
    const float* hidden = (const float*)d_in[0];   // [B, H]
    const float* enc    = (const float*)d_in[1];   // [B, T, H]
    const float* W      = (const float*)d_in[2];   // [H, H]
    // d_in[3] = bias: cancels under softmax, unused.
    float* out = (float*)d_out;                    // [B, 1, T]

    {
        dim3 grid(H / 32, B / 4, OCHUNKS);
        proj_hidden_kernel<<<grid, 256>>>(hidden, W);
    }
    {
        dim3 grid(T / NTILE, B);
        scores_kernel<<<grid, 256>>>(enc);
    }
    {
        dim3 grid(T / 1024, B);
        scale_kernel<<<grid, 256>>>(out);
    }
}